// round 7
// baseline (speedup 1.0000x reference)
#include <cuda_runtime.h>

namespace {

constexpr int Bn = 16;
constexpr int Ln = 2048;
constexpr int Gn = 8;
constexpr int Pn = 8;
constexpr int Kn = 64;
constexpr float kClamp = 15.0f;

constexpr int LT = 128;             // tile size; one thread per l
constexpr int NTb = Ln / LT;        // 16 tiles per batch
constexpr int GRID = Bn * NTb;      // 256 blocks
constexpr int THREADS = 128;
constexpr int DNs = 65;             // dn row stride: (li*65+k)%32 conflict-free

__device__ float g_partial[2][Bn][NTb][Pn];
__device__ unsigned g_cnt[Bn * 32];   // one counter per batch, 128B apart
__device__ unsigned g_gen[Bn * 32];

__device__ __forceinline__ float vldf(const float* p) { return *(volatile const float*)p; }

// Barrier over the NTb blocks of one batch only.
__device__ __forceinline__ void batch_sync(int b) {
    __syncthreads();
    if (threadIdx.x == 0) {
        __threadfence();
        volatile unsigned* genv = (volatile unsigned*)&g_gen[b * 32];
        unsigned cur = *genv;                       // snapshot BEFORE arrive
        if (atomicAdd(&g_cnt[b * 32], 1u) == NTb - 1) {
            atomicExch(&g_cnt[b * 32], 0u);
            __threadfence();
            atomicAdd(&g_gen[b * 32], 1u);
        } else {
            while (*genv == cur) { __nanosleep(64); }
            __threadfence();
        }
    }
    __syncthreads();
}

__global__ __launch_bounds__(THREADS, 4) void fused_kernel(
        const float* __restrict__ xp,
        const float* __restrict__ xn_in,
        const void*  __restrict__ mask_raw,
        const int*   __restrict__ am,
        float* out, int ofm) {
    __shared__ __align__(16) float dn_s[LT][DNs];   // native distances, row per thread
    __shared__ __align__(16) float bp_s[Kn][4];     // base pred coords (padded)
    __shared__ __align__(16) float bnv_s[Kn][4];    // base native coords (padded)
    __shared__ __align__(16) float red_s[Pn][LT + 4];
    __shared__ float ssum_s[Pn];
    __shared__ short pos_s[Ln];                     // position -> index in a0, else -1
    __shared__ unsigned char sig_s[Pn * Kn];        // sigma_j(k)
    __shared__ unsigned char mb_s[Kn];              // base mask values
    __shared__ int bj_s;

    const int tid = threadIdx.x;
    const int b = blockIdx.x / NTb;
    const int t = blockIdx.x % NTb;
    const int lg = t * LT + tid;

    float* xnat = out;
    float* mkf = out + Bn * Ln * 3;
    unsigned char* mkb = (unsigned char*)(out + Bn * Ln * 3);

    // ---- detect input-mask dtype (deterministic, per block) ----
    int all01 = 1, allf = 1;
    {
        const unsigned* mw = (const unsigned*)mask_raw;
        for (int i = tid; i < 1024; i += THREADS) {
            unsigned w = mw[i];
            if (w > 1u) all01 = 0;
            if (w != 0u && w != 0x3F800000u) allf = 0;
        }
    }
    all01 = __syncthreads_and(all01);
    allf  = __syncthreads_and(allf);
    const int mode = all01 ? 1 : (allf ? 2 : 0);

    // ---- init: each block seeds its OWN tile slice of out ----
    {
        const float* src = xn_in + (b * Ln + t * LT) * 3;
        float* dst = xnat + (b * Ln + t * LT) * 3;
        for (int i = tid; i < LT * 3; i += THREADS) dst[i] = src[i];
        int i = b * Ln + lg;
        int v;
        if (mode == 1)      v = ((const int*)mask_raw)[i] != 0;
        else if (mode == 2) v = ((const float*)mask_raw)[i] != 0.0f;
        else                v = ((const unsigned char*)mask_raw)[i] != 0;
        if (ofm) mkf[i] = v ? 1.0f : 0.0f;
        else     mkb[i] = (unsigned char)v;
    }

    // tile pred coords: immutable, hoisted out of the group loop
    const float px = __ldg(xp + (b * Ln + lg) * 3 + 0);
    const float py = __ldg(xp + (b * Ln + lg) * 3 + 1);
    const float pz = __ldg(xp + (b * Ln + lg) * 3 + 2);

    batch_sync(b);

    for (int g = 0; g < Gn; ++g) {
        const int* arow = am + g * Pn * Kn;

        for (int i = tid; i < Ln / 2; i += THREADS)
            ((unsigned*)pos_s)[i] = 0xFFFFFFFFu;    // pos = -1
        __syncthreads();

        if (tid < Kn) {
            int p0 = __ldg(arow + tid);
            pos_s[p0] = (short)tid;
            const float* q = xp + (b * Ln + p0) * 3;
            bp_s[tid][0] = __ldg(q + 0); bp_s[tid][1] = __ldg(q + 1); bp_s[tid][2] = __ldg(q + 2);
            const float* r = xnat + (b * Ln + p0) * 3;
            bnv_s[tid][0] = r[0]; bnv_s[tid][1] = r[1]; bnv_s[tid][2] = r[2];
            mb_s[tid] = ofm ? (unsigned char)(mkf[b * Ln + p0] != 0.0f)
                            : mkb[b * Ln + p0];
        }
        __syncthreads();

        // sigma_j(k) = index of a[j,k] within a0
        for (int i = tid; i < Pn * Kn; i += THREADS) {
            short m = pos_s[__ldg(arow + i)];
            sig_s[i] = (unsigned char)(m < 0 ? 0 : m);
        }
        const float cm = (pos_s[lg] >= 0) ? 0.0f : 1.0f;   // column mask, register-only
        const float nx = xnat[(b * Ln + lg) * 3 + 0];
        const float ny = xnat[(b * Ln + lg) * 3 + 1];
        const float nz = xnat[(b * Ln + lg) * 3 + 2];
        __syncthreads();

        // ---- fused distances: dp -> registers, dn -> own smem row ----
        float dpr[Kn];
        #pragma unroll
        for (int k = 0; k < Kn; ++k) {
            float4 bp4 = *(const float4*)bp_s[k];
            float dx = bp4.x - px, dy = bp4.y - py, dz = bp4.z - pz;
            dpr[k] = sqrtf(dx * dx + dy * dy + dz * dz);
            float4 bn4 = *(const float4*)bnv_s[k];
            float ex = bn4.x - nx, ey = bn4.y - ny, ez = bn4.z - nz;
            dn_s[tid][k] = sqrtf(ex * ex + ey * ey + ez * ez);
        }
        // no sync: each thread reads only its own dn row below

        const float* dnrow = dn_s[tid];
        const unsigned* sigw = (const unsigned*)sig_s;
        #pragma unroll 1
        for (int j = 0; j < Pn; ++j) {
            float acc = 0.0f;
            #pragma unroll
            for (int c = 0; c < Kn / 4; ++c) {
                unsigned w = sigw[j * (Kn / 4) + c];
                float d0 = dpr[4 * c + 0] - dnrow[w & 255u];
                acc += fminf(d0 * d0, kClamp);
                float d1 = dpr[4 * c + 1] - dnrow[(w >> 8) & 255u];
                acc += fminf(d1 * d1, kClamp);
                float d2 = dpr[4 * c + 2] - dnrow[(w >> 16) & 255u];
                acc += fminf(d2 * d2, kClamp);
                float d3 = dpr[4 * c + 3] - dnrow[w >> 24];
                acc += fminf(d3 * d3, kClamp);
            }
            red_s[j][tid] = acc * cm;
        }
        __syncthreads();

        if (tid < Pn) {
            const float4* rr = (const float4*)red_s[tid];
            float v = 0.0f;
            #pragma unroll
            for (int c = 0; c < LT / 4; ++c) {
                float4 q = rr[c];
                v += q.x + q.y + q.z + q.w;
            }
            g_partial[g & 1][b][t][tid] = v;
        }
        batch_sync(b);

        // ---- selection (redundant, bit-identical in every block of b) ----
        if (tid < Pn) {
            float v = 0.0f;
            for (int tt = 0; tt < NTb; ++tt)
                v += vldf(&g_partial[g & 1][b][tt][tid]);
            ssum_s[tid] = v;
        }
        __syncthreads();
        if (tid == 0) {
            float best = ssum_s[0];
            int bi = 0;
            for (int j = 1; j < Pn; ++j)
                if (ssum_s[j] < best) { best = ssum_s[j]; bi = j; }
            bj_s = bi;
        }
        __syncthreads();

        // ---- update (identical writes from every block of b; values from smem) ----
        if (tid < Kn) {
            int a0 = __ldg(arow + tid);
            int sk = sig_s[bj_s * Kn + tid];
            float* w = xnat + (b * Ln + a0) * 3;
            w[0] = bnv_s[sk][0]; w[1] = bnv_s[sk][1]; w[2] = bnv_s[sk][2];
            if (ofm) mkf[b * Ln + a0] = mb_s[sk] ? 1.0f : 0.0f;
            else     mkb[b * Ln + a0] = mb_s[sk];
        }
        __syncthreads();   // own update writes visible block-wide before next group
    }
}

} // namespace

extern "C" void kernel_launch(void* const* d_in, const int* in_sizes, int n_in,
                              void* d_out, int out_size) {
    const float* xp = (const float*)d_in[0];
    const float* xn = (const float*)d_in[1];
    const void* mask = d_in[2];
    const int* am = (const int*)d_in[3];
    float* out = (float*)d_out;

    (void)in_sizes; (void)n_in;

    const int ofm = (out_size == Bn * Ln * 3 + Bn * Ln) ? 1 : 0;

    fused_kernel<<<GRID, THREADS>>>(xp, xn, mask, am, out, ofm);
}

// round 8
// speedup vs baseline: 1.4963x; 1.4963x over previous
#include <cuda_runtime.h>

namespace {

constexpr int Bn = 16;
constexpr int Ln = 2048;
constexpr int Gn = 8;
constexpr int Pn = 8;
constexpr int Kn = 64;
constexpr float kClamp = 15.0f;

constexpr int LT = 128;             // tile size; thread pair (li, khalf)
constexpr int NTb = Ln / LT;        // 16 tiles per batch
constexpr int GRID = Bn * NTb;      // 256 blocks
constexpr int THREADS = 256;        // 128 li x 2 k-halves
constexpr int KH = Kn / 2;          // 32 k per half
constexpr int DNs = 65;             // dn row stride: (li+k)%32 conflict-free

__device__ float g_partial[2][Bn][NTb][Pn];
__device__ unsigned g_cnt[Bn * 32];
__device__ unsigned g_gen[Bn * 32];

__device__ __forceinline__ float vldf(const float* p) { return *(volatile const float*)p; }

// Barrier over the NTb blocks of one batch only.
__device__ __forceinline__ void batch_sync(int b) {
    __syncthreads();
    if (threadIdx.x == 0) {
        __threadfence();
        volatile unsigned* genv = (volatile unsigned*)&g_gen[b * 32];
        unsigned cur = *genv;                       // snapshot BEFORE arrive
        if (atomicAdd(&g_cnt[b * 32], 1u) == NTb - 1) {
            atomicExch(&g_cnt[b * 32], 0u);
            __threadfence();
            atomicAdd(&g_gen[b * 32], 1u);
        } else {
            while (*genv == cur) { __nanosleep(64); }
            __threadfence();
        }
    }
    __syncthreads();
}

__global__ __launch_bounds__(THREADS, 2) void fused_kernel(
        const float* __restrict__ xp,
        const float* __restrict__ xn_in,
        const void*  __restrict__ mask_raw,
        const int*   __restrict__ am,
        float* out, int ofm) {
    __shared__ __align__(16) float dn_s[LT][DNs];    // native distances
    __shared__ __align__(16) float bp_s[Kn][4];      // base pred coords (padded)
    __shared__ __align__(16) float bnv_s[Kn][4];     // base native coords (padded)
    __shared__ __align__(16) float red_s[Pn][2][LT]; // partial sums per (j, khalf, li)
    __shared__ float ssum_s[Pn];
    __shared__ short pos_s[Ln];
    __shared__ unsigned char sig_s[Pn * Kn];         // sigma_j(k) * 4 (byte offsets)
    __shared__ unsigned char mb_s[Kn];
    __shared__ int bj_s;

    const int tid = threadIdx.x;
    const int li = tid & (LT - 1);
    const int kh = tid >> 7;              // 0 or 1
    const int b = blockIdx.x / NTb;
    const int t = blockIdx.x % NTb;
    const int lg = t * LT + li;

    float* xnat = out;
    float* mkf = out + Bn * Ln * 3;
    unsigned char* mkb = (unsigned char*)(out + Bn * Ln * 3);

    // ---- detect input-mask dtype (deterministic, per block) ----
    int all01 = 1, allf = 1;
    {
        const unsigned* mw = (const unsigned*)mask_raw;
        for (int i = tid; i < 1024; i += THREADS) {
            unsigned w = mw[i];
            if (w > 1u) all01 = 0;
            if (w != 0u && w != 0x3F800000u) allf = 0;
        }
    }
    all01 = __syncthreads_and(all01);
    allf  = __syncthreads_and(allf);
    const int mode = all01 ? 1 : (allf ? 2 : 0);

    // ---- init: each block seeds its OWN tile slice of out ----
    {
        const float* src = xn_in + (b * Ln + t * LT) * 3;
        float* dst = xnat + (b * Ln + t * LT) * 3;
        for (int i = tid; i < LT * 3; i += THREADS) dst[i] = src[i];
        if (kh == 0) {
            int i = b * Ln + lg;
            int v;
            if (mode == 1)      v = ((const int*)mask_raw)[i] != 0;
            else if (mode == 2) v = ((const float*)mask_raw)[i] != 0.0f;
            else                v = ((const unsigned char*)mask_raw)[i] != 0;
            if (ofm) mkf[i] = v ? 1.0f : 0.0f;
            else     mkb[i] = (unsigned char)v;
        }
    }

    // tile pred coords: immutable, hoisted
    const float px = __ldg(xp + (b * Ln + lg) * 3 + 0);
    const float py = __ldg(xp + (b * Ln + lg) * 3 + 1);
    const float pz = __ldg(xp + (b * Ln + lg) * 3 + 2);

    batch_sync(b);

    for (int g = 0; g < Gn; ++g) {
        const int* arow = am + g * Pn * Kn;

        for (int i = tid; i < Ln / 2; i += THREADS)
            ((unsigned*)pos_s)[i] = 0xFFFFFFFFu;    // pos = -1
        __syncthreads();

        if (tid < Kn) {
            int p0 = __ldg(arow + tid);
            pos_s[p0] = (short)tid;
            const float* q = xp + (b * Ln + p0) * 3;
            bp_s[tid][0] = __ldg(q + 0); bp_s[tid][1] = __ldg(q + 1); bp_s[tid][2] = __ldg(q + 2);
            const float* r = xnat + (b * Ln + p0) * 3;
            bnv_s[tid][0] = r[0]; bnv_s[tid][1] = r[1]; bnv_s[tid][2] = r[2];
            mb_s[tid] = ofm ? (unsigned char)(mkf[b * Ln + p0] != 0.0f)
                            : mkb[b * Ln + p0];
        }
        __syncthreads();

        // sigma_j(k)*4 = byte offset of dn element within the row
        for (int i = tid; i < Pn * Kn; i += THREADS) {
            short m = pos_s[__ldg(arow + i)];
            sig_s[i] = (unsigned char)((m < 0 ? 0 : m) * 4);
        }
        const float cm = (pos_s[lg] >= 0) ? 0.0f : 1.0f;
        const float nx = xnat[(b * Ln + lg) * 3 + 0];
        const float ny = xnat[(b * Ln + lg) * 3 + 1];
        const float nz = xnat[(b * Ln + lg) * 3 + 2];
        __syncthreads();

        // ---- distances for own k-half: dp -> regs, dn -> smem ----
        float dpr[KH];
        #pragma unroll
        for (int kk = 0; kk < KH; ++kk) {
            const int k = kh * KH + kk;
            float4 bp4 = *(const float4*)bp_s[k];
            float dx = bp4.x - px, dy = bp4.y - py, dz = bp4.z - pz;
            dpr[kk] = sqrtf(dx * dx + dy * dy + dz * dz);
            float4 bn4 = *(const float4*)bnv_s[k];
            float ex = bn4.x - nx, ey = bn4.y - ny, ez = bn4.z - nz;
            dn_s[li][k] = sqrtf(ex * ex + ey * ey + ez * ez);
        }
        __syncthreads();   // cross-half dn reads below

        // ---- scores: own k-half, all j; 4 independent accumulators ----
        {
            const char* dnrow = (const char*)dn_s[li];
            const unsigned* sigw = (const unsigned*)sig_s;
            #pragma unroll 1
            for (int j = 0; j < Pn; ++j) {
                float a0 = 0.0f, a1 = 0.0f, a2 = 0.0f, a3 = 0.0f;
                #pragma unroll
                for (int c = 0; c < KH / 4; ++c) {
                    unsigned w = sigw[j * (Kn / 4) + kh * (KH / 4) + c];
                    float d0 = dpr[4 * c + 0] - *(const float*)(dnrow + (w & 255u));
                    a0 += fminf(d0 * d0, kClamp);
                    float d1 = dpr[4 * c + 1] - *(const float*)(dnrow + ((w >> 8) & 255u));
                    a1 += fminf(d1 * d1, kClamp);
                    float d2 = dpr[4 * c + 2] - *(const float*)(dnrow + ((w >> 16) & 255u));
                    a2 += fminf(d2 * d2, kClamp);
                    float d3 = dpr[4 * c + 3] - *(const float*)(dnrow + (w >> 24));
                    a3 += fminf(d3 * d3, kClamp);
                }
                red_s[j][kh][li] = ((a0 + a1) + (a2 + a3)) * cm;
            }
        }
        __syncthreads();

        if (tid < Pn) {
            const float4* r0 = (const float4*)red_s[tid][0];
            const float4* r1 = (const float4*)red_s[tid][1];
            float v = 0.0f;
            #pragma unroll
            for (int c = 0; c < LT / 4; ++c) {
                float4 q0 = r0[c], q1 = r1[c];
                v += (q0.x + q0.y + q0.z + q0.w) + (q1.x + q1.y + q1.z + q1.w);
            }
            g_partial[g & 1][b][t][tid] = v;
        }
        batch_sync(b);

        // ---- selection (redundant, bit-identical in every block of b) ----
        if (tid < Pn) {
            float v = 0.0f;
            for (int tt = 0; tt < NTb; ++tt)
                v += vldf(&g_partial[g & 1][b][tt][tid]);
            ssum_s[tid] = v;
        }
        __syncthreads();
        if (tid == 0) {
            float best = ssum_s[0];
            int bi = 0;
            for (int j = 1; j < Pn; ++j)
                if (ssum_s[j] < best) { best = ssum_s[j]; bi = j; }
            bj_s = bi;
        }
        __syncthreads();

        // ---- update (identical writes from every block of b) ----
        if (tid < Kn) {
            int a0i = __ldg(arow + tid);
            int sk = sig_s[bj_s * Kn + tid] >> 2;
            float* w = xnat + (b * Ln + a0i) * 3;
            w[0] = bnv_s[sk][0]; w[1] = bnv_s[sk][1]; w[2] = bnv_s[sk][2];
            if (ofm) mkf[b * Ln + a0i] = mb_s[sk] ? 1.0f : 0.0f;
            else     mkb[b * Ln + a0i] = mb_s[sk];
        }
        __syncthreads();   // own update writes visible block-wide before next group
    }
}

} // namespace

extern "C" void kernel_launch(void* const* d_in, const int* in_sizes, int n_in,
                              void* d_out, int out_size) {
    const float* xp = (const float*)d_in[0];
    const float* xn = (const float*)d_in[1];
    const void* mask = d_in[2];
    const int* am = (const int*)d_in[3];
    float* out = (float*)d_out;

    (void)in_sizes; (void)n_in;

    const int ofm = (out_size == Bn * Ln * 3 + Bn * Ln) ? 1 : 0;

    fused_kernel<<<GRID, THREADS>>>(xp, xn, mask, am, out, ofm);
}

// round 9
// speedup vs baseline: 1.6072x; 1.0741x over previous
#include <cuda_runtime.h>

namespace {

constexpr int Bn = 16;
constexpr int Ln = 2048;
constexpr int Gn = 8;
constexpr int Pn = 8;
constexpr int Kn = 64;
constexpr float kClamp = 15.0f;

constexpr int LT = 128;             // tile size (one li per thread-column)
constexpr int NTb = Ln / LT;        // 16 tiles per batch
constexpr int GRID = Bn * NTb;      // 256 blocks
constexpr int THREADS = 512;        // 128 li x 4 k-quarters
constexpr int NKQ = 4;
constexpr int KQ = Kn / NKQ;        // 16 k per thread
constexpr int NW = THREADS / 32;    // 16 warps
constexpr int DNs = 65;             // dn row stride: (li+k)%32 conflict-free

__device__ float g_partial[2][Bn][NTb][Pn];
__device__ unsigned g_cnt[Bn * 32];
__device__ unsigned g_gen[Bn * 32];

__device__ __forceinline__ float vldf(const float* p) { return *(volatile const float*)p; }

// Barrier over the NTb blocks of one batch only.
__device__ __forceinline__ void batch_sync(int b) {
    __syncthreads();
    if (threadIdx.x == 0) {
        __threadfence();
        volatile unsigned* genv = (volatile unsigned*)&g_gen[b * 32];
        unsigned cur = *genv;                       // snapshot BEFORE arrive
        if (atomicAdd(&g_cnt[b * 32], 1u) == NTb - 1) {
            atomicExch(&g_cnt[b * 32], 0u);
            __threadfence();
            atomicAdd(&g_gen[b * 32], 1u);
        } else {
            while (*genv == cur) { __nanosleep(64); }
            __threadfence();
        }
    }
    __syncthreads();
}

__global__ __launch_bounds__(THREADS, 2) void fused_kernel(
        const float* __restrict__ xp,
        const float* __restrict__ xn_in,
        const void*  __restrict__ mask_raw,
        const int*   __restrict__ am,
        float* out, int ofm) {
    __shared__ __align__(16) float dn_s[LT][DNs];    // native distances
    __shared__ __align__(16) float bp_s[Kn][4];      // base pred coords (padded)
    __shared__ __align__(16) float bnv_s[Kn][4];     // base native coords (padded)
    __shared__ float red_s[Pn][NW];                  // warp-reduced partials
    __shared__ float ssum_s[Pn];
    __shared__ short pos_s[Ln];
    __shared__ unsigned char sig_s[Pn * Kn];         // sigma_j(k) * 4 (byte offsets)
    __shared__ unsigned char mb_s[Kn];
    __shared__ int bj_s;

    const int tid = threadIdx.x;
    const int li = tid & (LT - 1);
    const int kq = tid >> 7;              // 0..3
    const int wid = tid >> 5;             // 0..15
    const int lane = tid & 31;
    const int b = blockIdx.x / NTb;
    const int t = blockIdx.x % NTb;
    const int lg = t * LT + li;

    float* xnat = out;
    float* mkf = out + Bn * Ln * 3;
    unsigned char* mkb = (unsigned char*)(out + Bn * Ln * 3);

    // ---- detect input-mask dtype (deterministic, per block) ----
    int all01 = 1, allf = 1;
    {
        const unsigned* mw = (const unsigned*)mask_raw;
        for (int i = tid; i < 1024; i += THREADS) {
            unsigned w = mw[i];
            if (w > 1u) all01 = 0;
            if (w != 0u && w != 0x3F800000u) allf = 0;
        }
    }
    all01 = __syncthreads_and(all01);
    allf  = __syncthreads_and(allf);
    const int mode = all01 ? 1 : (allf ? 2 : 0);

    // ---- init: each block seeds its OWN tile slice of out ----
    {
        const float* src = xn_in + (b * Ln + t * LT) * 3;
        float* dst = xnat + (b * Ln + t * LT) * 3;
        for (int i = tid; i < LT * 3; i += THREADS) dst[i] = src[i];
        if (kq == 0) {
            int i = b * Ln + lg;
            int v;
            if (mode == 1)      v = ((const int*)mask_raw)[i] != 0;
            else if (mode == 2) v = ((const float*)mask_raw)[i] != 0.0f;
            else                v = ((const unsigned char*)mask_raw)[i] != 0;
            if (ofm) mkf[i] = v ? 1.0f : 0.0f;
            else     mkb[i] = (unsigned char)v;
        }
    }

    // tile pred coords: immutable, hoisted
    const float px = __ldg(xp + (b * Ln + lg) * 3 + 0);
    const float py = __ldg(xp + (b * Ln + lg) * 3 + 1);
    const float pz = __ldg(xp + (b * Ln + lg) * 3 + 2);

    batch_sync(b);

    for (int g = 0; g < Gn; ++g) {
        const int* arow = am + g * Pn * Kn;

        for (int i = tid; i < Ln / 2; i += THREADS)
            ((unsigned*)pos_s)[i] = 0xFFFFFFFFu;    // pos = -1
        __syncthreads();

        if (tid < Kn) {
            int p0 = __ldg(arow + tid);
            pos_s[p0] = (short)tid;
            const float* q = xp + (b * Ln + p0) * 3;
            bp_s[tid][0] = __ldg(q + 0); bp_s[tid][1] = __ldg(q + 1); bp_s[tid][2] = __ldg(q + 2);
            const float* r = xnat + (b * Ln + p0) * 3;
            bnv_s[tid][0] = r[0]; bnv_s[tid][1] = r[1]; bnv_s[tid][2] = r[2];
            mb_s[tid] = ofm ? (unsigned char)(mkf[b * Ln + p0] != 0.0f)
                            : mkb[b * Ln + p0];
        }
        __syncthreads();

        // sigma_j(k)*4 = byte offset of dn element within the row
        if (tid < Pn * Kn) {
            short m = pos_s[__ldg(arow + tid)];
            sig_s[tid] = (unsigned char)((m < 0 ? 0 : m) * 4);
        }
        const float cm = (pos_s[lg] >= 0) ? 0.0f : 1.0f;
        const float nx = xnat[(b * Ln + lg) * 3 + 0];
        const float ny = xnat[(b * Ln + lg) * 3 + 1];
        const float nz = xnat[(b * Ln + lg) * 3 + 2];
        __syncthreads();

        // ---- distances for own k-quarter: dp -> regs, dn -> smem ----
        float dpr[KQ];
        #pragma unroll
        for (int kk = 0; kk < KQ; ++kk) {
            const int k = kq * KQ + kk;
            float4 bp4 = *(const float4*)bp_s[k];
            float dx = bp4.x - px, dy = bp4.y - py, dz = bp4.z - pz;
            dpr[kk] = sqrtf(dx * dx + dy * dy + dz * dz);
            float4 bn4 = *(const float4*)bnv_s[k];
            float ex = bn4.x - nx, ey = bn4.y - ny, ez = bn4.z - nz;
            dn_s[li][k] = sqrtf(ex * ex + ey * ey + ez * ez);
        }
        __syncthreads();   // cross-quarter dn reads below

        // ---- scores: own k-quarter, all j; warp-shuffle reduce over li ----
        {
            const char* dnrow = (const char*)dn_s[li];
            const unsigned* sigw = (const unsigned*)sig_s;
            #pragma unroll 1
            for (int j = 0; j < Pn; ++j) {
                float a0 = 0.0f, a1 = 0.0f, a2 = 0.0f, a3 = 0.0f;
                #pragma unroll
                for (int c = 0; c < KQ / 4; ++c) {
                    unsigned w = sigw[j * (Kn / 4) + kq * (KQ / 4) + c];
                    float d0 = dpr[4 * c + 0] - *(const float*)(dnrow + (w & 255u));
                    a0 += fminf(d0 * d0, kClamp);
                    float d1 = dpr[4 * c + 1] - *(const float*)(dnrow + ((w >> 8) & 255u));
                    a1 += fminf(d1 * d1, kClamp);
                    float d2 = dpr[4 * c + 2] - *(const float*)(dnrow + ((w >> 16) & 255u));
                    a2 += fminf(d2 * d2, kClamp);
                    float d3 = dpr[4 * c + 3] - *(const float*)(dnrow + (w >> 24));
                    a3 += fminf(d3 * d3, kClamp);
                }
                float acc = ((a0 + a1) + (a2 + a3)) * cm;
                #pragma unroll
                for (int s = 16; s > 0; s >>= 1)
                    acc += __shfl_xor_sync(0xFFFFFFFFu, acc, s);
                if (lane == 0) red_s[j][wid] = acc;
            }
        }
        __syncthreads();

        if (tid < Pn) {
            float v = 0.0f;
            #pragma unroll
            for (int wchunk = 0; wchunk < NW; ++wchunk) v += red_s[tid][wchunk];
            g_partial[g & 1][b][t][tid] = v;
        }
        batch_sync(b);

        // ---- selection (redundant, bit-identical in every block of b) ----
        if (tid < Pn) {
            float v = 0.0f;
            for (int tt = 0; tt < NTb; ++tt)
                v += vldf(&g_partial[g & 1][b][tt][tid]);
            ssum_s[tid] = v;
        }
        __syncthreads();
        if (tid == 0) {
            float best = ssum_s[0];
            int bi = 0;
            for (int j = 1; j < Pn; ++j)
                if (ssum_s[j] < best) { best = ssum_s[j]; bi = j; }
            bj_s = bi;
        }
        __syncthreads();

        // ---- update (identical writes from every block of b) ----
        if (tid < Kn) {
            int a0i = __ldg(arow + tid);
            int sk = sig_s[bj_s * Kn + tid] >> 2;
            float* w = xnat + (b * Ln + a0i) * 3;
            w[0] = bnv_s[sk][0]; w[1] = bnv_s[sk][1]; w[2] = bnv_s[sk][2];
            if (ofm) mkf[b * Ln + a0i] = mb_s[sk] ? 1.0f : 0.0f;
            else     mkb[b * Ln + a0i] = mb_s[sk];
        }
        __syncthreads();   // own update writes visible block-wide before next group
    }
}

} // namespace

extern "C" void kernel_launch(void* const* d_in, const int* in_sizes, int n_in,
                              void* d_out, int out_size) {
    const float* xp = (const float*)d_in[0];
    const float* xn = (const float*)d_in[1];
    const void* mask = d_in[2];
    const int* am = (const int*)d_in[3];
    float* out = (float*)d_out;

    (void)in_sizes; (void)n_in;

    const int ofm = (out_size == Bn * Ln * 3 + Bn * Ln) ? 1 : 0;

    fused_kernel<<<GRID, THREADS>>>(xp, xn, mask, am, out, ofm);
}